// round 1
// baseline (speedup 1.0000x reference)
#include <cuda_runtime.h>
#include <math.h>

#define BB 2
#define LL 8192
#define CC 256
#define KW 17
#define HALFW 8
#define NLEV 4

// ---------------- device scratch (no allocations allowed) ----------------
__device__ float g_xcat[BB * LL * 2 * CC];        // [x[t-1], x[t]]
__device__ float g_wcat[CC * 2 * CC];             // [W0 | W1] repacked
__device__ float g_h[BB * LL * CC];               // current level input
__device__ float g_qkv[BB * LL * 3 * CC];         // qkv for current level
__device__ float g_ov[BB * LL * CC];              // o + v
__device__ float g_lev0[BB * LL * CC];
__device__ float g_lev1[BB * (LL / 2) * CC];
__device__ float g_lev2[BB * (LL / 4) * CC];
__device__ float g_lev3[BB * (LL / 8) * CC];
__device__ float g_logits[BB * LL];
__device__ float g_gattn[BB * LL];
__device__ float g_ctx[BB * NLEV * CC];
__device__ float g_film[BB * 2 * CC];

// ---------------- helpers ----------------
__device__ __forceinline__ float sigmoidf_(float x) { return 1.0f / (1.0f + expf(-x)); }

// ---------------- build [x[t-1], x[t]] rows ----------------
__global__ void build_xcat_kernel(const float* __restrict__ x) {
    int idx = blockIdx.x * blockDim.x + threadIdx.x;   // over B*L*C
    if (idx >= BB * LL * CC) return;
    int c = idx % CC;
    int bt = idx / CC;
    int t = bt % LL;
    float prev = (t > 0) ? x[idx - CC] : 0.0f;
    g_xcat[(size_t)bt * (2 * CC) + c] = prev;
    g_xcat[(size_t)bt * (2 * CC) + CC + c] = x[idx];
}

// stem_w (C, C, 2) -> wcat (C, 2C) with [W0 | W1]
__global__ void repack_wcat_kernel(const float* __restrict__ stem_w) {
    int idx = blockIdx.x * blockDim.x + threadIdx.x;   // over C*C
    if (idx >= CC * CC) return;
    int o = idx / CC, i = idx % CC;
    g_wcat[o * (2 * CC) + i] = stem_w[idx * 2 + 0];
    g_wcat[o * (2 * CC) + CC + i] = stem_w[idx * 2 + 1];
}

// ---------------- SGEMM: C[m,n] = sum_k A[m,k]*B[n,k] (+bias[n]) ----------------
// 64x64 tile, BK=16, 256 threads, 4x4 microtile. M%64==0, N%64==0, K%16==0.
__global__ void __launch_bounds__(256) sgemm_nt(const float* __restrict__ A,
                                                const float* __restrict__ Bm,
                                                const float* __restrict__ bias,
                                                float* __restrict__ C,
                                                int M, int N, int K) {
    __shared__ float As[16][68];
    __shared__ float Bs[16][68];
    const int tid = threadIdx.x;
    const int m0 = blockIdx.y * 64;
    const int n0 = blockIdx.x * 64;
    const int lr = tid >> 2;           // 0..63
    const int lk = (tid & 3) << 2;     // 0,4,8,12
    const int tx = tid & 15;
    const int ty = tid >> 4;

    float acc[4][4];
#pragma unroll
    for (int i = 0; i < 4; i++)
#pragma unroll
        for (int j = 0; j < 4; j++) acc[i][j] = 0.0f;

    const float* Ap = A + (size_t)(m0 + lr) * K + lk;
    const float* Bp = Bm + (size_t)(n0 + lr) * K + lk;

    for (int k0 = 0; k0 < K; k0 += 16) {
        float4 av = *reinterpret_cast<const float4*>(Ap + k0);
        float4 bv = *reinterpret_cast<const float4*>(Bp + k0);
        As[lk + 0][lr] = av.x; As[lk + 1][lr] = av.y;
        As[lk + 2][lr] = av.z; As[lk + 3][lr] = av.w;
        Bs[lk + 0][lr] = bv.x; Bs[lk + 1][lr] = bv.y;
        Bs[lk + 2][lr] = bv.z; Bs[lk + 3][lr] = bv.w;
        __syncthreads();
#pragma unroll
        for (int kk = 0; kk < 16; kk++) {
            float4 a4 = *reinterpret_cast<const float4*>(&As[kk][ty << 2]);
            float4 b4 = *reinterpret_cast<const float4*>(&Bs[kk][tx << 2]);
            float avr[4] = {a4.x, a4.y, a4.z, a4.w};
            float bvr[4] = {b4.x, b4.y, b4.z, b4.w};
#pragma unroll
            for (int i = 0; i < 4; i++)
#pragma unroll
                for (int j = 0; j < 4; j++) acc[i][j] = fmaf(avr[i], bvr[j], acc[i][j]);
        }
        __syncthreads();
    }

    float bb[4] = {0.f, 0.f, 0.f, 0.f};
    if (bias) {
#pragma unroll
        for (int j = 0; j < 4; j++) bb[j] = bias[n0 + (tx << 2) + j];
    }
#pragma unroll
    for (int i = 0; i < 4; i++) {
        float4 r;
        r.x = acc[i][0] + bb[0];
        r.y = acc[i][1] + bb[1];
        r.z = acc[i][2] + bb[2];
        r.w = acc[i][3] + bb[3];
        *reinterpret_cast<float4*>(C + (size_t)(m0 + (ty << 2) + i) * N + n0 + (tx << 2)) = r;
    }
}

// ---------------- windowed attention: one warp per position ----------------
// qkv rows: [q(256) k(256) v(256)]; ov = softmax-attn(v_window) + v
__global__ void attn_kernel(const float* __restrict__ h,
                            const float* __restrict__ qkv,
                            const float* __restrict__ width_w,
                            const float* __restrict__ width_b,
                            float* __restrict__ ov,
                            int l) {
    int gwarp = (blockIdx.x * blockDim.x + threadIdx.x) >> 5;
    int lane = threadIdx.x & 31;
    if (gwarp >= BB * l) return;
    int b = gwarp / l;
    int t = gwarp - b * l;

    const float* hrow = h + (size_t)gwarp * CC;
    const float* qrow = qkv + (size_t)gwarp * (3 * CC);

    float q[8];
    float wsum = 0.0f;
#pragma unroll
    for (int j = 0; j < 8; j++) {
        int c = lane + 32 * j;
        q[j] = qrow[c];
        wsum = fmaf(hrow[c], width_w[c], wsum);
    }
#pragma unroll
    for (int o = 16; o > 0; o >>= 1) wsum += __shfl_xor_sync(0xffffffffu, wsum, o);
    float width = sigmoidf_(wsum + width_b[0]) * (float)HALFW + 0.5f;

    float scores[KW];
#pragma unroll
    for (int w = 0; w < KW; w++) {
        int kt = t - HALFW + w;
        float s = 0.0f;
        if (kt >= 0 && kt < l) {
            const float* krow = qkv + ((size_t)(b * l + kt)) * (3 * CC) + CC;
#pragma unroll
            for (int j = 0; j < 8; j++) s = fmaf(q[j], krow[lane + 32 * j], s);
        }
#pragma unroll
        for (int o = 16; o > 0; o >>= 1) s += __shfl_xor_sync(0xffffffffu, s, o);
        float rel = fabsf((float)(w - HALFW));
        float mask = sigmoidf_((width - rel) * 5.0f);
        scores[w] = s * 0.0625f - (1.0f - mask) * 10000.0f;
    }

    float mx = scores[0];
#pragma unroll
    for (int w = 1; w < KW; w++) mx = fmaxf(mx, scores[w]);
    float denom = 0.0f;
#pragma unroll
    for (int w = 0; w < KW; w++) { scores[w] = expf(scores[w] - mx); denom += scores[w]; }
    float inv = 1.0f / denom;

    float oacc[8];
    const float* vself = qrow + 2 * CC;
#pragma unroll
    for (int j = 0; j < 8; j++) oacc[j] = vself[lane + 32 * j];   // "+ v"
#pragma unroll
    for (int w = 0; w < KW; w++) {
        int kt = t - HALFW + w;
        if (kt < 0 || kt >= l) continue;
        float a = scores[w] * inv;
        const float* vrow = qkv + ((size_t)(b * l + kt)) * (3 * CC) + 2 * CC;
#pragma unroll
        for (int j = 0; j < 8; j++) oacc[j] = fmaf(a, vrow[lane + 32 * j], oacc[j]);
    }
    float* orow = ov + (size_t)gwarp * CC;
#pragma unroll
    for (int j = 0; j < 8; j++) orow[lane + 32 * j] = oacc[j];
}

// ---------------- mean-pool by 2 ----------------
__global__ void downsample_kernel(const float* __restrict__ src, float* __restrict__ dst, int lsrc) {
    int idx = blockIdx.x * blockDim.x + threadIdx.x;  // over B*(lsrc/2)*C
    int ldst = lsrc / 2;
    int total = BB * ldst * CC;
    if (idx >= total) return;
    int c = idx % CC;
    int bt = idx / CC;
    int t = bt % ldst;
    int b = bt / ldst;
    const float* s0 = src + ((size_t)(b * lsrc + 2 * t)) * CC + c;
    dst[idx] = 0.5f * (s0[0] + s0[CC]);
}

// ---------------- global attention logits: one warp per (b,t) ----------------
__global__ void logits_kernel(const float* __restrict__ query) {
    int gwarp = (blockIdx.x * blockDim.x + threadIdx.x) >> 5;
    int lane = threadIdx.x & 31;
    if (gwarp >= BB * LL) return;
    int b = gwarp / LL;
    int t = gwarp - b * LL;
    float s = 0.0f;
#pragma unroll
    for (int j = 0; j < 8; j++) {
        int c = lane + 32 * j;
        s = fmaf(g_lev0[((size_t)(b * LL + t)) * CC + c],            query[c],            s);
        s = fmaf(g_lev1[((size_t)(b * (LL/2) + (t >> 1))) * CC + c], query[CC + c],       s);
        s = fmaf(g_lev2[((size_t)(b * (LL/4) + (t >> 2))) * CC + c], query[2 * CC + c],   s);
        s = fmaf(g_lev3[((size_t)(b * (LL/8) + (t >> 3))) * CC + c], query[3 * CC + c],   s);
    }
#pragma unroll
    for (int o = 16; o > 0; o >>= 1) s += __shfl_xor_sync(0xffffffffu, s, o);
    if (lane == 0) g_logits[gwarp] = s;
}

// ---------------- softmax over L per batch (one block per batch) ----------------
__global__ void softmax_kernel() {
    __shared__ float sl[LL];
    __shared__ float red[256];
    int b = blockIdx.x;
    int tid = threadIdx.x;
    const float* lg = g_logits + (size_t)b * LL;
    float mx = -1e30f;
    for (int t = tid; t < LL; t += 256) { float v = lg[t]; sl[t] = v; mx = fmaxf(mx, v); }
    red[tid] = mx; __syncthreads();
    for (int o = 128; o > 0; o >>= 1) { if (tid < o) red[tid] = fmaxf(red[tid], red[tid + o]); __syncthreads(); }
    mx = red[0]; __syncthreads();
    float sum = 0.0f;
    for (int t = tid; t < LL; t += 256) { float e = expf(sl[t] - mx); sl[t] = e; sum += e; }
    red[tid] = sum; __syncthreads();
    for (int o = 128; o > 0; o >>= 1) { if (tid < o) red[tid] += red[tid + o]; __syncthreads(); }
    float inv = 1.0f / red[0];
    for (int t = tid; t < LL; t += 256) g_gattn[(size_t)b * LL + t] = sl[t] * inv;
}

// ---------------- ctx[b, i*256+c] = sum_l gattn[b,l] * lev_i[b, l>>i, c] ----------------
__global__ void ctx_kernel() {
    int i = blockIdx.x;   // level
    int b = blockIdx.y;
    int c = threadIdx.x;  // 0..255
    const float* lev = (i == 0) ? g_lev0 : (i == 1) ? g_lev1 : (i == 2) ? g_lev2 : g_lev3;
    int li = LL >> i;
    const float* ga = g_gattn + (size_t)b * LL;
    const float* base = lev + (size_t)b * li * CC + c;
    float a0 = 0.f, a1 = 0.f, a2 = 0.f, a3 = 0.f;
    for (int t = 0; t < LL; t += 4) {
        a0 = fmaf(ga[t + 0], base[(size_t)((t + 0) >> i) * CC], a0);
        a1 = fmaf(ga[t + 1], base[(size_t)((t + 1) >> i) * CC], a1);
        a2 = fmaf(ga[t + 2], base[(size_t)((t + 2) >> i) * CC], a2);
        a3 = fmaf(ga[t + 3], base[(size_t)((t + 3) >> i) * CC], a3);
    }
    g_ctx[(size_t)b * (NLEV * CC) + i * CC + c] = (a0 + a1) + (a2 + a3);
}

// ---------------- FiLM: film[b,o] = ctx[b,:] . film_w[o,:] + film_b[o] ----------------
__global__ void film_kernel(const float* __restrict__ film_w, const float* __restrict__ film_b) {
    __shared__ float sc[NLEV * CC];
    int b = blockIdx.x;
    int o = threadIdx.x;  // 0..511
    for (int d = o; d < NLEV * CC; d += 512) sc[d] = g_ctx[(size_t)b * (NLEV * CC) + d];
    __syncthreads();
    const float* wr = film_w + (size_t)o * (NLEV * CC);
    float acc = 0.0f;
#pragma unroll 8
    for (int d = 0; d < NLEV * CC; d++) acc = fmaf(sc[d], wr[d], acc);
    g_film[(size_t)b * (2 * CC) + o] = acc + film_b[o];
}

// ---------------- final: out = lev0 * (1 + scale) + bias ----------------
__global__ void final_kernel(float* __restrict__ out) {
    int idx = blockIdx.x * blockDim.x + threadIdx.x;
    if (idx >= BB * LL * CC) return;
    int c = idx % CC;
    int b = idx / (LL * CC);
    float sc = g_film[(size_t)b * (2 * CC) + c];
    float bi = g_film[(size_t)b * (2 * CC) + CC + c];
    out[idx] = fmaf(g_lev0[idx], 1.0f + sc, bi);
}

// ---------------- launch ----------------
extern "C" void kernel_launch(void* const* d_in, const int* in_sizes, int n_in,
                              void* d_out, int out_size) {
    const float* x       = (const float*)d_in[0];
    const float* stem_w  = (const float*)d_in[1];
    const float* stem_b  = (const float*)d_in[2];
    const float* qkv_w   = (const float*)d_in[3];
    const float* width_w = (const float*)d_in[4];
    const float* width_b = (const float*)d_in[5];
    const float* out_w   = (const float*)d_in[6];
    const float* query   = (const float*)d_in[7];
    const float* film_w  = (const float*)d_in[8];
    const float* film_b  = (const float*)d_in[9];
    float* out = (float*)d_out;

    float *p_xcat, *p_wcat, *p_h, *p_qkv, *p_ov, *p_lev[4];
    cudaGetSymbolAddress((void**)&p_xcat, g_xcat);
    cudaGetSymbolAddress((void**)&p_wcat, g_wcat);
    cudaGetSymbolAddress((void**)&p_h, g_h);
    cudaGetSymbolAddress((void**)&p_qkv, g_qkv);
    cudaGetSymbolAddress((void**)&p_ov, g_ov);
    cudaGetSymbolAddress((void**)&p_lev[0], g_lev0);
    cudaGetSymbolAddress((void**)&p_lev[1], g_lev1);
    cudaGetSymbolAddress((void**)&p_lev[2], g_lev2);
    cudaGetSymbolAddress((void**)&p_lev[3], g_lev3);

    // stem
    build_xcat_kernel<<<(BB * LL * CC + 255) / 256, 256>>>(x);
    repack_wcat_kernel<<<(CC * CC + 255) / 256, 256>>>(stem_w);
    {
        dim3 grid(CC / 64, (BB * LL) / 64);
        sgemm_nt<<<grid, 256>>>(p_xcat, p_wcat, stem_b, p_h, BB * LL, CC, 2 * CC);
    }

    // levels
    for (int i = 0; i < NLEV; i++) {
        int l = LL >> i;
        int M = BB * l;
        {
            dim3 grid((3 * CC) / 64, M / 64);
            sgemm_nt<<<grid, 256>>>(p_h, qkv_w, nullptr, p_qkv, M, 3 * CC, CC);
        }
        attn_kernel<<<M / 8, 256>>>(p_h, p_qkv, width_w, width_b, p_ov, l);
        {
            dim3 grid(CC / 64, M / 64);
            sgemm_nt<<<grid, 256>>>(p_ov, out_w, nullptr, p_lev[i], M, CC, CC);
        }
        if (i < NLEV - 1) {
            int tot = BB * (l / 2) * CC;
            downsample_kernel<<<(tot + 255) / 256, 256>>>(p_lev[i], p_h, l);
        }
    }

    // global attention + FiLM
    logits_kernel<<<(BB * LL) / 8, 256>>>(query);
    softmax_kernel<<<BB, 256>>>();
    ctx_kernel<<<dim3(NLEV, BB), CC>>>();
    film_kernel<<<BB, 2 * CC>>>(film_w, film_b);
    final_kernel<<<(BB * LL * CC + 255) / 256, 256>>>(out);
}

// round 2
// speedup vs baseline: 1.4628x; 1.4628x over previous
#include <cuda_runtime.h>
#include <math.h>

#define BB 2
#define LL 8192
#define CC 256
#define KW 17
#define HALFW 8
#define NLEV 4
#define CTX_CHUNKS 32

// ---------------- device scratch (no allocations allowed) ----------------
__device__ float g_xcat[BB * LL * 2 * CC];
__device__ float g_wcat[CC * 2 * CC];
__device__ float g_h[BB * LL * CC];
__device__ float g_qkv[BB * LL * 3 * CC];
__device__ float g_ov[BB * LL * CC];
__device__ float g_lev0[BB * LL * CC];
__device__ float g_lev1[BB * (LL / 2) * CC];
__device__ float g_lev2[BB * (LL / 4) * CC];
__device__ float g_lev3[BB * (LL / 8) * CC];
__device__ float g_logits[BB * LL];
__device__ float g_gattn[BB * LL];
__device__ float g_ctxpart[NLEV * BB * CTX_CHUNKS * CC];
__device__ float g_ctx[BB * NLEV * CC];
__device__ float g_film[BB * 2 * CC];

__device__ __forceinline__ float sigmoidf_(float x) { return 1.0f / (1.0f + expf(-x)); }

// ---------------- build [x[t-1], x[t]] rows ----------------
__global__ void build_xcat_kernel(const float* __restrict__ x) {
    int idx = blockIdx.x * blockDim.x + threadIdx.x;
    if (idx >= BB * LL * CC) return;
    int c = idx % CC;
    int bt = idx / CC;
    int t = bt % LL;
    float prev = (t > 0) ? x[idx - CC] : 0.0f;
    g_xcat[(size_t)bt * (2 * CC) + c] = prev;
    g_xcat[(size_t)bt * (2 * CC) + CC + c] = x[idx];
}

__global__ void repack_wcat_kernel(const float* __restrict__ stem_w) {
    int idx = blockIdx.x * blockDim.x + threadIdx.x;
    if (idx >= CC * CC) return;
    int o = idx / CC, i = idx % CC;
    g_wcat[o * (2 * CC) + i] = stem_w[idx * 2 + 0];
    g_wcat[o * (2 * CC) + CC + i] = stem_w[idx * 2 + 1];
}

// ---------------- SGEMM 128x128, BK=8, 8x8 microtile, double-buffered ----
// C[m,n] = sum_k A[m,k] * B[n,k] (+ bias[n]).  M%128==0, N%128==0, K%8==0.
#define BM 128
#define BN 128
#define BKK 8
#define SPAD 132

__global__ void __launch_bounds__(256) sgemm128(const float* __restrict__ A,
                                                const float* __restrict__ Bm,
                                                const float* __restrict__ bias,
                                                float* __restrict__ C,
                                                int M, int N, int K) {
    __shared__ float As[2][BKK][SPAD];
    __shared__ float Bs[2][BKK][SPAD];

    const int tid = threadIdx.x;
    const int m0 = blockIdx.y * BM;
    const int n0 = blockIdx.x * BN;
    const int tx = tid & 15;          // 0..15  (n)
    const int ty = tid >> 4;          // 0..15  (m)

    // global load mapping: each thread loads one float4 of A and one of B per tile
    const int lr = tid >> 1;              // 0..127
    const int lk = (tid & 1) << 2;        // 0 or 4

    const float* Ap = A + (size_t)(m0 + lr) * K + lk;
    const float* Bp = Bm + (size_t)(n0 + lr) * K + lk;

    float acc[8][8];
#pragma unroll
    for (int i = 0; i < 8; i++)
#pragma unroll
        for (int j = 0; j < 8; j++) acc[i][j] = 0.0f;

    // prologue: load first tile into buf 0
    {
        float4 av = *reinterpret_cast<const float4*>(Ap);
        float4 bv = *reinterpret_cast<const float4*>(Bp);
        As[0][lk + 0][lr] = av.x; As[0][lk + 1][lr] = av.y;
        As[0][lk + 2][lr] = av.z; As[0][lk + 3][lr] = av.w;
        Bs[0][lk + 0][lr] = bv.x; Bs[0][lk + 1][lr] = bv.y;
        Bs[0][lk + 2][lr] = bv.z; Bs[0][lk + 3][lr] = bv.w;
    }
    __syncthreads();

    int buf = 0;
    for (int k0 = 0; k0 < K; k0 += BKK) {
        const int nk = k0 + BKK;
        float4 av, bv;
        if (nk < K) {
            av = *reinterpret_cast<const float4*>(Ap + nk);
            bv = *reinterpret_cast<const float4*>(Bp + nk);
        }
#pragma unroll
        for (int kk = 0; kk < BKK; kk++) {
            float4 a0 = *reinterpret_cast<const float4*>(&As[buf][kk][ty << 2]);
            float4 a1 = *reinterpret_cast<const float4*>(&As[buf][kk][64 + (ty << 2)]);
            float4 b0 = *reinterpret_cast<const float4*>(&Bs[buf][kk][tx << 2]);
            float4 b1 = *reinterpret_cast<const float4*>(&Bs[buf][kk][64 + (tx << 2)]);
            float ar[8] = {a0.x, a0.y, a0.z, a0.w, a1.x, a1.y, a1.z, a1.w};
            float br[8] = {b0.x, b0.y, b0.z, b0.w, b1.x, b1.y, b1.z, b1.w};
#pragma unroll
            for (int i = 0; i < 8; i++)
#pragma unroll
                for (int j = 0; j < 8; j++) acc[i][j] = fmaf(ar[i], br[j], acc[i][j]);
        }
        if (nk < K) {
            int nb = buf ^ 1;
            As[nb][lk + 0][lr] = av.x; As[nb][lk + 1][lr] = av.y;
            As[nb][lk + 2][lr] = av.z; As[nb][lk + 3][lr] = av.w;
            Bs[nb][lk + 0][lr] = bv.x; Bs[nb][lk + 1][lr] = bv.y;
            Bs[nb][lk + 2][lr] = bv.z; Bs[nb][lk + 3][lr] = bv.w;
            __syncthreads();
            buf = nb;
        }
    }

    float bb[8] = {0.f, 0.f, 0.f, 0.f, 0.f, 0.f, 0.f, 0.f};
    if (bias) {
#pragma unroll
        for (int j = 0; j < 4; j++) {
            bb[j] = bias[n0 + (tx << 2) + j];
            bb[4 + j] = bias[n0 + 64 + (tx << 2) + j];
        }
    }
#pragma unroll
    for (int half = 0; half < 2; half++) {
#pragma unroll
        for (int i = 0; i < 4; i++) {
            int row = m0 + half * 64 + (ty << 2) + i;
            float* crow = C + (size_t)row * N + n0;
            float4 r0, r1;
            r0.x = acc[half * 4 + i][0] + bb[0];
            r0.y = acc[half * 4 + i][1] + bb[1];
            r0.z = acc[half * 4 + i][2] + bb[2];
            r0.w = acc[half * 4 + i][3] + bb[3];
            r1.x = acc[half * 4 + i][4] + bb[4];
            r1.y = acc[half * 4 + i][5] + bb[5];
            r1.z = acc[half * 4 + i][6] + bb[6];
            r1.w = acc[half * 4 + i][7] + bb[7];
            *reinterpret_cast<float4*>(crow + (tx << 2)) = r0;
            *reinterpret_cast<float4*>(crow + 64 + (tx << 2)) = r1;
        }
    }
}

// ---------------- windowed attention: one warp per position ----------------
__global__ void attn_kernel(const float* __restrict__ h,
                            const float* __restrict__ qkv,
                            const float* __restrict__ width_w,
                            const float* __restrict__ width_b,
                            float* __restrict__ ov,
                            int l) {
    int gwarp = (blockIdx.x * blockDim.x + threadIdx.x) >> 5;
    int lane = threadIdx.x & 31;
    if (gwarp >= BB * l) return;
    int b = gwarp / l;
    int t = gwarp - b * l;

    const float* hrow = h + (size_t)gwarp * CC;
    const float* qrow = qkv + (size_t)gwarp * (3 * CC);

    float q[8];
    float wsum = 0.0f;
#pragma unroll
    for (int j = 0; j < 8; j++) {
        int c = lane + 32 * j;
        q[j] = qrow[c];
        wsum = fmaf(hrow[c], width_w[c], wsum);
    }
#pragma unroll
    for (int o = 16; o > 0; o >>= 1) wsum += __shfl_xor_sync(0xffffffffu, wsum, o);
    float width = sigmoidf_(wsum + width_b[0]) * (float)HALFW + 0.5f;

    float scores[KW];
#pragma unroll
    for (int w = 0; w < KW; w++) {
        int kt = t - HALFW + w;
        float s = 0.0f;
        if (kt >= 0 && kt < l) {
            const float* krow = qkv + ((size_t)(b * l + kt)) * (3 * CC) + CC;
#pragma unroll
            for (int j = 0; j < 8; j++) s = fmaf(q[j], krow[lane + 32 * j], s);
        }
#pragma unroll
        for (int o = 16; o > 0; o >>= 1) s += __shfl_xor_sync(0xffffffffu, s, o);
        float rel = fabsf((float)(w - HALFW));
        float mask = sigmoidf_((width - rel) * 5.0f);
        scores[w] = s * 0.0625f - (1.0f - mask) * 10000.0f;
    }

    float mx = scores[0];
#pragma unroll
    for (int w = 1; w < KW; w++) mx = fmaxf(mx, scores[w]);
    float denom = 0.0f;
#pragma unroll
    for (int w = 0; w < KW; w++) { scores[w] = expf(scores[w] - mx); denom += scores[w]; }
    float inv = 1.0f / denom;

    float oacc[8];
    const float* vself = qrow + 2 * CC;
#pragma unroll
    for (int j = 0; j < 8; j++) oacc[j] = vself[lane + 32 * j];
#pragma unroll
    for (int w = 0; w < KW; w++) {
        int kt = t - HALFW + w;
        if (kt < 0 || kt >= l) continue;
        float a = scores[w] * inv;
        const float* vrow = qkv + ((size_t)(b * l + kt)) * (3 * CC) + 2 * CC;
#pragma unroll
        for (int j = 0; j < 8; j++) oacc[j] = fmaf(a, vrow[lane + 32 * j], oacc[j]);
    }
    float* orow = ov + (size_t)gwarp * CC;
#pragma unroll
    for (int j = 0; j < 8; j++) orow[lane + 32 * j] = oacc[j];
}

// ---------------- mean-pool by 2 ----------------
__global__ void downsample_kernel(const float* __restrict__ src, float* __restrict__ dst, int lsrc) {
    int idx = blockIdx.x * blockDim.x + threadIdx.x;
    int ldst = lsrc / 2;
    int total = BB * ldst * CC;
    if (idx >= total) return;
    int c = idx % CC;
    int bt = idx / CC;
    int t = bt % ldst;
    int b = bt / ldst;
    const float* s0 = src + ((size_t)(b * lsrc + 2 * t)) * CC + c;
    dst[idx] = 0.5f * (s0[0] + s0[CC]);
}

// ---------------- global attention logits ----------------
__global__ void logits_kernel(const float* __restrict__ query) {
    int gwarp = (blockIdx.x * blockDim.x + threadIdx.x) >> 5;
    int lane = threadIdx.x & 31;
    if (gwarp >= BB * LL) return;
    int b = gwarp / LL;
    int t = gwarp - b * LL;
    float s = 0.0f;
#pragma unroll
    for (int j = 0; j < 8; j++) {
        int c = lane + 32 * j;
        s = fmaf(g_lev0[((size_t)(b * LL + t)) * CC + c],            query[c],          s);
        s = fmaf(g_lev1[((size_t)(b * (LL/2) + (t >> 1))) * CC + c], query[CC + c],     s);
        s = fmaf(g_lev2[((size_t)(b * (LL/4) + (t >> 2))) * CC + c], query[2 * CC + c], s);
        s = fmaf(g_lev3[((size_t)(b * (LL/8) + (t >> 3))) * CC + c], query[3 * CC + c], s);
    }
#pragma unroll
    for (int o = 16; o > 0; o >>= 1) s += __shfl_xor_sync(0xffffffffu, s, o);
    if (lane == 0) g_logits[gwarp] = s;
}

// ---------------- softmax over L per batch ----------------
__global__ void softmax_kernel() {
    __shared__ float sl[LL];
    __shared__ float red[256];
    int b = blockIdx.x;
    int tid = threadIdx.x;
    const float* lg = g_logits + (size_t)b * LL;
    float mx = -1e30f;
    for (int t = tid; t < LL; t += 256) { float v = lg[t]; sl[t] = v; mx = fmaxf(mx, v); }
    red[tid] = mx; __syncthreads();
    for (int o = 128; o > 0; o >>= 1) { if (tid < o) red[tid] = fmaxf(red[tid], red[tid + o]); __syncthreads(); }
    mx = red[0]; __syncthreads();
    float sum = 0.0f;
    for (int t = tid; t < LL; t += 256) { float e = expf(sl[t] - mx); sl[t] = e; sum += e; }
    red[tid] = sum; __syncthreads();
    for (int o = 128; o > 0; o >>= 1) { if (tid < o) red[tid] += red[tid + o]; __syncthreads(); }
    float inv = 1.0f / red[0];
    for (int t = tid; t < LL; t += 256) g_gattn[(size_t)b * LL + t] = sl[t] * inv;
}

// ---------------- ctx partial reduction: 256 blocks ----------------
__global__ void ctx_part_kernel() {
    int i = blockIdx.x;    // level
    int b = blockIdx.y;
    int ch = blockIdx.z;
    int c = threadIdx.x;   // 0..255
    const float* lev = (i == 0) ? g_lev0 : (i == 1) ? g_lev1 : (i == 2) ? g_lev2 : g_lev3;
    int li = LL >> i;
    const float* ga = g_gattn + (size_t)b * LL;
    const float* base = lev + (size_t)b * li * CC + c;
    const int span = LL / CTX_CHUNKS;          // 256
    const int t0 = ch * span;
    float a0 = 0.f, a1 = 0.f, a2 = 0.f, a3 = 0.f;
    for (int t = t0; t < t0 + span; t += 4) {
        a0 = fmaf(ga[t + 0], base[(size_t)((t + 0) >> i) * CC], a0);
        a1 = fmaf(ga[t + 1], base[(size_t)((t + 1) >> i) * CC], a1);
        a2 = fmaf(ga[t + 2], base[(size_t)((t + 2) >> i) * CC], a2);
        a3 = fmaf(ga[t + 3], base[(size_t)((t + 3) >> i) * CC], a3);
    }
    g_ctxpart[(((size_t)i * BB + b) * CTX_CHUNKS + ch) * CC + c] = (a0 + a1) + (a2 + a3);
}

__global__ void ctx_reduce_kernel() {
    int i = blockIdx.x;
    int b = blockIdx.y;
    int c = threadIdx.x;
    const float* p = g_ctxpart + (((size_t)i * BB + b) * CTX_CHUNKS) * CC + c;
    float s = 0.0f;
#pragma unroll
    for (int ch = 0; ch < CTX_CHUNKS; ch++) s += p[(size_t)ch * CC];
    g_ctx[(size_t)b * (NLEV * CC) + i * CC + c] = s;
}

// ---------------- FiLM ----------------
__global__ void film_kernel(const float* __restrict__ film_w, const float* __restrict__ film_b) {
    __shared__ float sc[NLEV * CC];
    int b = blockIdx.x;
    int o = threadIdx.x;
    for (int d = o; d < NLEV * CC; d += 512) sc[d] = g_ctx[(size_t)b * (NLEV * CC) + d];
    __syncthreads();
    const float* wr = film_w + (size_t)o * (NLEV * CC);
    float acc = 0.0f;
#pragma unroll 8
    for (int d = 0; d < NLEV * CC; d++) acc = fmaf(sc[d], wr[d], acc);
    g_film[(size_t)b * (2 * CC) + o] = acc + film_b[o];
}

// ---------------- final ----------------
__global__ void final_kernel(float* __restrict__ out) {
    int idx = blockIdx.x * blockDim.x + threadIdx.x;
    if (idx >= BB * LL * CC) return;
    int c = idx % CC;
    int b = idx / (LL * CC);
    float sc = g_film[(size_t)b * (2 * CC) + c];
    float bi = g_film[(size_t)b * (2 * CC) + CC + c];
    out[idx] = fmaf(g_lev0[idx], 1.0f + sc, bi);
}

// ---------------- launch ----------------
extern "C" void kernel_launch(void* const* d_in, const int* in_sizes, int n_in,
                              void* d_out, int out_size) {
    const float* x       = (const float*)d_in[0];
    const float* stem_w  = (const float*)d_in[1];
    const float* stem_b  = (const float*)d_in[2];
    const float* qkv_w   = (const float*)d_in[3];
    const float* width_w = (const float*)d_in[4];
    const float* width_b = (const float*)d_in[5];
    const float* out_w   = (const float*)d_in[6];
    const float* query   = (const float*)d_in[7];
    const float* film_w  = (const float*)d_in[8];
    const float* film_b  = (const float*)d_in[9];
    float* out = (float*)d_out;

    float *p_xcat, *p_wcat, *p_h, *p_qkv, *p_ov, *p_lev[4];
    cudaGetSymbolAddress((void**)&p_xcat, g_xcat);
    cudaGetSymbolAddress((void**)&p_wcat, g_wcat);
    cudaGetSymbolAddress((void**)&p_h, g_h);
    cudaGetSymbolAddress((void**)&p_qkv, g_qkv);
    cudaGetSymbolAddress((void**)&p_ov, g_ov);
    cudaGetSymbolAddress((void**)&p_lev[0], g_lev0);
    cudaGetSymbolAddress((void**)&p_lev[1], g_lev1);
    cudaGetSymbolAddress((void**)&p_lev[2], g_lev2);
    cudaGetSymbolAddress((void**)&p_lev[3], g_lev3);

    // stem
    build_xcat_kernel<<<(BB * LL * CC + 255) / 256, 256>>>(x);
    repack_wcat_kernel<<<(CC * CC + 255) / 256, 256>>>(stem_w);
    {
        dim3 grid(CC / BN, (BB * LL) / BM);
        sgemm128<<<grid, 256>>>(p_xcat, p_wcat, stem_b, p_h, BB * LL, CC, 2 * CC);
    }

    // levels
    for (int i = 0; i < NLEV; i++) {
        int l = LL >> i;
        int M = BB * l;
        {
            dim3 grid((3 * CC) / BN, M / BM);
            sgemm128<<<grid, 256>>>(p_h, qkv_w, nullptr, p_qkv, M, 3 * CC, CC);
        }
        attn_kernel<<<M / 8, 256>>>(p_h, p_qkv, width_w, width_b, p_ov, l);
        {
            dim3 grid(CC / BN, M / BM);
            sgemm128<<<grid, 256>>>(p_ov, out_w, nullptr, p_lev[i], M, CC, CC);
        }
        if (i < NLEV - 1) {
            int tot = BB * (l / 2) * CC;
            downsample_kernel<<<(tot + 255) / 256, 256>>>(p_lev[i], p_h, l);
        }
    }

    // global attention + FiLM
    logits_kernel<<<(BB * LL) / 8, 256>>>(query);
    softmax_kernel<<<BB, 256>>>();
    ctx_part_kernel<<<dim3(NLEV, BB, CTX_CHUNKS), CC>>>();
    ctx_reduce_kernel<<<dim3(NLEV, BB), CC>>>();
    film_kernel<<<BB, 2 * CC>>>(film_w, film_b);
    final_kernel<<<(BB * LL * CC + 255) / 256, 256>>>(out);
}

// round 4
// speedup vs baseline: 1.6175x; 1.1057x over previous
#include <cuda_runtime.h>
#include <cuda_bf16.h>
#include <math.h>
#include <stdint.h>

#define BB 2
#define LL 8192
#define CC 256
#define KW 17
#define HALFW 8
#define NLEV 4
#define CTX_CHUNKS 32

__device__ __forceinline__ uint32_t smem_to_u32(const void* p) {
    uint32_t a;
    asm("{ .reg .u64 t; cvta.to.shared.u64 t, %1; cvt.u32.u64 %0, t; }" : "=r"(a) : "l"(p));
    return a;
}

// ================= device scratch =================
__device__ float g_h[BB * LL * CC];
__device__ float g_qkv[BB * LL * 3 * CC];
__device__ float g_ov[BB * LL * CC];
__device__ float g_lev0[BB * LL * CC];
__device__ float g_lev1[BB * (LL / 2) * CC];
__device__ float g_lev2[BB * (LL / 4) * CC];
__device__ float g_lev3[BB * (LL / 8) * CC];
__device__ float g_logits[BB * LL];
__device__ float g_gattn[BB * LL];
__device__ float g_ctxpart[NLEV * BB * CTX_CHUNKS * CC];
__device__ float g_ctx[BB * NLEV * CC];
__device__ float g_film[BB * 2 * CC];

__device__ __nv_bfloat16 g_a2[(size_t)BB * LL * 3 * 512];   // activations split (max: stem K'=1536)
__device__ __nv_bfloat16 g_w2stem[CC * 3 * 512];            // 256 x 1536
__device__ __nv_bfloat16 g_w2qkv[3 * CC * 3 * CC];          // 768 x 768
__device__ __nv_bfloat16 g_w2out[CC * 3 * CC];              // 256 x 768

__device__ __forceinline__ float sigmoidf_(float x) { return 1.0f / (1.0f + expf(-x)); }

// ================= hi/lo split conversions =================
// A-side layout per row: [hi | hi | lo] ; B-side: [hi | lo | hi]
__device__ __forceinline__ void split2(float x, __nv_bfloat16& h, __nv_bfloat16& l) {
    h = __float2bfloat16(x);
    l = __float2bfloat16(x - __bfloat162float(h));
}

__global__ void split_act_kernel(const float* __restrict__ X, __nv_bfloat16* __restrict__ Y,
                                 int total, int K) {
    int idx = blockIdx.x * blockDim.x + threadIdx.x;
    if (idx >= total) return;
    int m = idx / K, k = idx - m * K;
    __nv_bfloat16 h, l; split2(X[idx], h, l);
    size_t base = (size_t)m * 3 * K;
    Y[base + k] = h; Y[base + K + k] = h; Y[base + 2 * K + k] = l;
}

__global__ void split_wgt_kernel(const float* __restrict__ X, __nv_bfloat16* __restrict__ Y,
                                 int total, int K) {
    int idx = blockIdx.x * blockDim.x + threadIdx.x;
    if (idx >= total) return;
    int m = idx / K, k = idx - m * K;
    __nv_bfloat16 h, l; split2(X[idx], h, l);
    size_t base = (size_t)m * 3 * K;
    Y[base + k] = h; Y[base + K + k] = l; Y[base + 2 * K + k] = h;
}

// stem activation: row m=(b,t), K=512: [x[b,t-1,:] (0 if t==0) | x[b,t,:]], A-side split
__global__ void split_stem_act_kernel(const float* __restrict__ x) {
    int idx = blockIdx.x * blockDim.x + threadIdx.x;    // over B*L*512
    if (idx >= BB * LL * 512) return;
    int k = idx & 511;
    int m = idx >> 9;
    int t = m % LL;
    float v;
    if (k < CC) v = (t > 0) ? x[(size_t)(m - 1) * CC + k] : 0.0f;
    else        v = x[(size_t)m * CC + (k - CC)];
    __nv_bfloat16 h, l; split2(v, h, l);
    size_t base = (size_t)m * 1536;
    g_a2[base + k] = h; g_a2[base + 512 + k] = h; g_a2[base + 1024 + k] = l;
}

// stem weight: row o, K=512: col k<256 -> stem_w[o,k,0], else stem_w[o,k-256,1]; B-side split
__global__ void split_stem_wgt_kernel(const float* __restrict__ stem_w) {
    int idx = blockIdx.x * blockDim.x + threadIdx.x;    // over 256*512
    if (idx >= CC * 512) return;
    int k = idx & 511;
    int o = idx >> 9;
    int i = k & 255, tap = (k < CC) ? 0 : 1;
    float v = stem_w[(size_t)o * 512 + i * 2 + tap];
    __nv_bfloat16 h, l; split2(v, h, l);
    size_t base = (size_t)o * 1536;
    g_w2stem[base + k] = h; g_w2stem[base + 512 + k] = l; g_w2stem[base + 1024 + k] = h;
}

// ================= HMMA bf16 GEMM (mma.sync, family-portable) =================
// C[M,N] = A2[M,Kp] * B2[N,Kp]^T (+bias). M,N % 128 == 0, Kp % 32 == 0.
// 128x128 CTA tile, BK=32, 8 warps (2x4), warp tile 64x32, double-buffered smem.
#define BK 32
#define SP 40   // smem pitch in bf16 (80B: 16B-aligned, ldmatrix conflict-free)

__global__ void __launch_bounds__(256) gemm_mma(const __nv_bfloat16* __restrict__ A2,
                                                const __nv_bfloat16* __restrict__ B2,
                                                const float* __restrict__ bias,
                                                float* __restrict__ C,
                                                int M, int N, int Kp) {
    __shared__ __align__(16) __nv_bfloat16 As[2][128][SP];
    __shared__ __align__(16) __nv_bfloat16 Bs[2][128][SP];

    const int tid = threadIdx.x;
    const int lane = tid & 31;
    const int wid = tid >> 5;
    const int wm = (wid >> 2) * 64;     // warp m offset in tile
    const int wn = (wid & 3) * 32;      // warp n offset in tile
    const int m0 = blockIdx.y * 128;
    const int n0 = blockIdx.x * 128;

    float acc[4][4][4];
#pragma unroll
    for (int i = 0; i < 4; i++)
#pragma unroll
        for (int j = 0; j < 4; j++)
#pragma unroll
            for (int r = 0; r < 4; r++) acc[i][j][r] = 0.0f;

    // global load mapping: each thread: 2x uint4 from A, 2x from B
    const int lrow = tid >> 1;
    const int lk = (tid & 1) * 16;
    const __nv_bfloat16* Ag = A2 + (size_t)(m0 + lrow) * Kp + lk;
    const __nv_bfloat16* Bg = B2 + (size_t)(n0 + lrow) * Kp + lk;

    // preload tile 0
    {
        uint4 a0 = *reinterpret_cast<const uint4*>(Ag);
        uint4 a1 = *reinterpret_cast<const uint4*>(Ag + 8);
        uint4 b0 = *reinterpret_cast<const uint4*>(Bg);
        uint4 b1 = *reinterpret_cast<const uint4*>(Bg + 8);
        *reinterpret_cast<uint4*>(&As[0][lrow][lk]) = a0;
        *reinterpret_cast<uint4*>(&As[0][lrow][lk + 8]) = a1;
        *reinterpret_cast<uint4*>(&Bs[0][lrow][lk]) = b0;
        *reinterpret_cast<uint4*>(&Bs[0][lrow][lk + 8]) = b1;
    }
    __syncthreads();

    // ldmatrix lane addressing (within warp tile)
    const int arow = lane & 15;                 // A: rows 0..15 of the 16-row frag
    const int akoff = (lane >> 4) << 3;         // A: k sub-offset 0 or 8
    const int brow = lane & 7;                  // B: rows 0..7 (lanes 0..15 used)
    const int bkoff = ((lane >> 3) & 1) << 3;

    const int NT = Kp / BK;
    for (int it = 0; it < NT; it++) {
        const int buf = it & 1;
        uint4 a0v, a1v, b0v, b1v;
        const bool more = (it + 1) < NT;
        if (more) {
            const int ko = (it + 1) * BK;
            a0v = *reinterpret_cast<const uint4*>(Ag + ko);
            a1v = *reinterpret_cast<const uint4*>(Ag + ko + 8);
            b0v = *reinterpret_cast<const uint4*>(Bg + ko);
            b1v = *reinterpret_cast<const uint4*>(Bg + ko + 8);
        }
#pragma unroll
        for (int ks = 0; ks < 2; ks++) {
            uint32_t af[4][4];
            uint32_t bf[4][2];
#pragma unroll
            for (int mt = 0; mt < 4; mt++) {
                uint32_t addr = smem_to_u32(&As[buf][wm + mt * 16 + arow][ks * 16 + akoff]);
                asm volatile("ldmatrix.sync.aligned.m8n8.x4.shared.b16 {%0,%1,%2,%3}, [%4];"
                             : "=r"(af[mt][0]), "=r"(af[mt][1]), "=r"(af[mt][2]), "=r"(af[mt][3])
                             : "r"(addr));
            }
#pragma unroll
            for (int nt = 0; nt < 4; nt++) {
                uint32_t addr = smem_to_u32(&Bs[buf][wn + nt * 8 + brow][ks * 16 + bkoff]);
                asm volatile("ldmatrix.sync.aligned.m8n8.x2.shared.b16 {%0,%1}, [%2];"
                             : "=r"(bf[nt][0]), "=r"(bf[nt][1])
                             : "r"(addr));
            }
#pragma unroll
            for (int mt = 0; mt < 4; mt++)
#pragma unroll
                for (int nt = 0; nt < 4; nt++) {
                    asm volatile(
                        "mma.sync.aligned.m16n8k16.row.col.f32.bf16.bf16.f32 "
                        "{%0,%1,%2,%3}, {%4,%5,%6,%7}, {%8,%9}, {%0,%1,%2,%3};"
                        : "+f"(acc[mt][nt][0]), "+f"(acc[mt][nt][1]),
                          "+f"(acc[mt][nt][2]), "+f"(acc[mt][nt][3])
                        : "r"(af[mt][0]), "r"(af[mt][1]), "r"(af[mt][2]), "r"(af[mt][3]),
                          "r"(bf[nt][0]), "r"(bf[nt][1]));
                }
        }
        if (more) {
            __syncthreads();
            const int nb = buf ^ 1;
            *reinterpret_cast<uint4*>(&As[nb][lrow][lk]) = a0v;
            *reinterpret_cast<uint4*>(&As[nb][lrow][lk + 8]) = a1v;
            *reinterpret_cast<uint4*>(&Bs[nb][lrow][lk]) = b0v;
            *reinterpret_cast<uint4*>(&Bs[nb][lrow][lk + 8]) = b1v;
            __syncthreads();
        }
    }

    // epilogue
    const int g = lane >> 2;
    const int t = lane & 3;
#pragma unroll
    for (int mt = 0; mt < 4; mt++) {
#pragma unroll
        for (int nt = 0; nt < 4; nt++) {
            int row = m0 + wm + mt * 16 + g;
            int col = n0 + wn + nt * 8 + 2 * t;
            float b0 = 0.f, b1 = 0.f;
            if (bias) { b0 = bias[col]; b1 = bias[col + 1]; }
            float2 v0, v1;
            v0.x = acc[mt][nt][0] + b0; v0.y = acc[mt][nt][1] + b1;
            v1.x = acc[mt][nt][2] + b0; v1.y = acc[mt][nt][3] + b1;
            *reinterpret_cast<float2*>(C + (size_t)row * N + col) = v0;
            *reinterpret_cast<float2*>(C + (size_t)(row + 8) * N + col) = v1;
        }
    }
}

// ================= windowed attention =================
__global__ void attn_kernel(const float* __restrict__ h,
                            const float* __restrict__ qkv,
                            const float* __restrict__ width_w,
                            const float* __restrict__ width_b,
                            float* __restrict__ ov,
                            int l) {
    int gwarp = (blockIdx.x * blockDim.x + threadIdx.x) >> 5;
    int lane = threadIdx.x & 31;
    if (gwarp >= BB * l) return;
    int b = gwarp / l;
    int t = gwarp - b * l;

    const float* hrow = h + (size_t)gwarp * CC;
    const float* qrow = qkv + (size_t)gwarp * (3 * CC);

    float q[8];
    float wsum = 0.0f;
#pragma unroll
    for (int j = 0; j < 8; j++) {
        int c = lane + 32 * j;
        q[j] = qrow[c];
        wsum = fmaf(hrow[c], width_w[c], wsum);
    }
#pragma unroll
    for (int o = 16; o > 0; o >>= 1) wsum += __shfl_xor_sync(0xffffffffu, wsum, o);
    float width = sigmoidf_(wsum + width_b[0]) * (float)HALFW + 0.5f;

    float scores[KW];
#pragma unroll
    for (int w = 0; w < KW; w++) {
        int kt = t - HALFW + w;
        float s = 0.0f;
        if (kt >= 0 && kt < l) {
            const float* krow = qkv + ((size_t)(b * l + kt)) * (3 * CC) + CC;
#pragma unroll
            for (int j = 0; j < 8; j++) s = fmaf(q[j], krow[lane + 32 * j], s);
        }
#pragma unroll
        for (int o = 16; o > 0; o >>= 1) s += __shfl_xor_sync(0xffffffffu, s, o);
        float rel = fabsf((float)(w - HALFW));
        float mask = sigmoidf_((width - rel) * 5.0f);
        scores[w] = s * 0.0625f - (1.0f - mask) * 10000.0f;
    }

    float mx = scores[0];
#pragma unroll
    for (int w = 1; w < KW; w++) mx = fmaxf(mx, scores[w]);
    float denom = 0.0f;
#pragma unroll
    for (int w = 0; w < KW; w++) { scores[w] = expf(scores[w] - mx); denom += scores[w]; }
    float inv = 1.0f / denom;

    float oacc[8];
    const float* vself = qrow + 2 * CC;
#pragma unroll
    for (int j = 0; j < 8; j++) oacc[j] = vself[lane + 32 * j];
#pragma unroll
    for (int w = 0; w < KW; w++) {
        int kt = t - HALFW + w;
        if (kt < 0 || kt >= l) continue;
        float a = scores[w] * inv;
        const float* vrow = qkv + ((size_t)(b * l + kt)) * (3 * CC) + 2 * CC;
#pragma unroll
        for (int j = 0; j < 8; j++) oacc[j] = fmaf(a, vrow[lane + 32 * j], oacc[j]);
    }
    float* orow = ov + (size_t)gwarp * CC;
#pragma unroll
    for (int j = 0; j < 8; j++) orow[lane + 32 * j] = oacc[j];
}

// ================= mean-pool by 2 =================
__global__ void downsample_kernel(const float* __restrict__ src, float* __restrict__ dst, int lsrc) {
    int idx = blockIdx.x * blockDim.x + threadIdx.x;
    int ldst = lsrc / 2;
    int total = BB * ldst * CC;
    if (idx >= total) return;
    int c = idx % CC;
    int bt = idx / CC;
    int t = bt % ldst;
    int b = bt / ldst;
    const float* s0 = src + ((size_t)(b * lsrc + 2 * t)) * CC + c;
    dst[idx] = 0.5f * (s0[0] + s0[CC]);
}

// ================= global attention logits =================
__global__ void logits_kernel(const float* __restrict__ query) {
    int gwarp = (blockIdx.x * blockDim.x + threadIdx.x) >> 5;
    int lane = threadIdx.x & 31;
    if (gwarp >= BB * LL) return;
    int b = gwarp / LL;
    int t = gwarp - b * LL;
    float s = 0.0f;
#pragma unroll
    for (int j = 0; j < 8; j++) {
        int c = lane + 32 * j;
        s = fmaf(g_lev0[((size_t)(b * LL + t)) * CC + c],            query[c],          s);
        s = fmaf(g_lev1[((size_t)(b * (LL/2) + (t >> 1))) * CC + c], query[CC + c],     s);
        s = fmaf(g_lev2[((size_t)(b * (LL/4) + (t >> 2))) * CC + c], query[2 * CC + c], s);
        s = fmaf(g_lev3[((size_t)(b * (LL/8) + (t >> 3))) * CC + c], query[3 * CC + c], s);
    }
#pragma unroll
    for (int o = 16; o > 0; o >>= 1) s += __shfl_xor_sync(0xffffffffu, s, o);
    if (lane == 0) g_logits[gwarp] = s;
}

// ================= softmax over L per batch =================
__global__ void softmax_kernel() {
    __shared__ float sl[LL];
    __shared__ float red[256];
    int b = blockIdx.x;
    int tid = threadIdx.x;
    const float* lg = g_logits + (size_t)b * LL;
    float mx = -1e30f;
    for (int t = tid; t < LL; t += 256) { float v = lg[t]; sl[t] = v; mx = fmaxf(mx, v); }
    red[tid] = mx; __syncthreads();
    for (int o = 128; o > 0; o >>= 1) { if (tid < o) red[tid] = fmaxf(red[tid], red[tid + o]); __syncthreads(); }
    mx = red[0]; __syncthreads();
    float sum = 0.0f;
    for (int t = tid; t < LL; t += 256) { float e = expf(sl[t] - mx); sl[t] = e; sum += e; }
    red[tid] = sum; __syncthreads();
    for (int o = 128; o > 0; o >>= 1) { if (tid < o) red[tid] += red[tid + o]; __syncthreads(); }
    float inv = 1.0f / red[0];
    for (int t = tid; t < LL; t += 256) g_gattn[(size_t)b * LL + t] = sl[t] * inv;
}

// ================= ctx partial reduction =================
__global__ void ctx_part_kernel() {
    int i = blockIdx.x;
    int b = blockIdx.y;
    int ch = blockIdx.z;
    int c = threadIdx.x;
    const float* lev = (i == 0) ? g_lev0 : (i == 1) ? g_lev1 : (i == 2) ? g_lev2 : g_lev3;
    int li = LL >> i;
    const float* ga = g_gattn + (size_t)b * LL;
    const float* base = lev + (size_t)b * li * CC + c;
    const int span = LL / CTX_CHUNKS;
    const int t0 = ch * span;
    float a0 = 0.f, a1 = 0.f, a2 = 0.f, a3 = 0.f;
    for (int t = t0; t < t0 + span; t += 4) {
        a0 = fmaf(ga[t + 0], base[(size_t)((t + 0) >> i) * CC], a0);
        a1 = fmaf(ga[t + 1], base[(size_t)((t + 1) >> i) * CC], a1);
        a2 = fmaf(ga[t + 2], base[(size_t)((t + 2) >> i) * CC], a2);
        a3 = fmaf(ga[t + 3], base[(size_t)((t + 3) >> i) * CC], a3);
    }
    g_ctxpart[(((size_t)i * BB + b) * CTX_CHUNKS + ch) * CC + c] = (a0 + a1) + (a2 + a3);
}

__global__ void ctx_reduce_kernel() {
    int i = blockIdx.x;
    int b = blockIdx.y;
    int c = threadIdx.x;
    const float* p = g_ctxpart + (((size_t)i * BB + b) * CTX_CHUNKS) * CC + c;
    float s = 0.0f;
#pragma unroll
    for (int ch = 0; ch < CTX_CHUNKS; ch++) s += p[(size_t)ch * CC];
    g_ctx[(size_t)b * (NLEV * CC) + i * CC + c] = s;
}

// ================= FiLM =================
__global__ void film_kernel(const float* __restrict__ film_w, const float* __restrict__ film_b) {
    __shared__ float sc[NLEV * CC];
    int b = blockIdx.x;
    int o = threadIdx.x;
    for (int d = o; d < NLEV * CC; d += 512) sc[d] = g_ctx[(size_t)b * (NLEV * CC) + d];
    __syncthreads();
    const float* wr = film_w + (size_t)o * (NLEV * CC);
    float acc = 0.0f;
#pragma unroll 8
    for (int d = 0; d < NLEV * CC; d++) acc = fmaf(sc[d], wr[d], acc);
    g_film[(size_t)b * (2 * CC) + o] = acc + film_b[o];
}

// ================= final =================
__global__ void final_kernel(float* __restrict__ out) {
    int idx = blockIdx.x * blockDim.x + threadIdx.x;
    if (idx >= BB * LL * CC) return;
    int c = idx % CC;
    int b = idx / (LL * CC);
    float sc = g_film[(size_t)b * (2 * CC) + c];
    float bi = g_film[(size_t)b * (2 * CC) + CC + c];
    out[idx] = fmaf(g_lev0[idx], 1.0f + sc, bi);
}

// ================= launch =================
extern "C" void kernel_launch(void* const* d_in, const int* in_sizes, int n_in,
                              void* d_out, int out_size) {
    const float* x       = (const float*)d_in[0];
    const float* stem_w  = (const float*)d_in[1];
    const float* stem_b  = (const float*)d_in[2];
    const float* qkv_w   = (const float*)d_in[3];
    const float* width_w = (const float*)d_in[4];
    const float* width_b = (const float*)d_in[5];
    const float* out_w   = (const float*)d_in[6];
    const float* query   = (const float*)d_in[7];
    const float* film_w  = (const float*)d_in[8];
    const float* film_b  = (const float*)d_in[9];
    float* out = (float*)d_out;

    float *p_h, *p_qkv, *p_ov, *p_lev[4];
    __nv_bfloat16 *p_a2, *p_w2stem, *p_w2qkv, *p_w2out;
    cudaGetSymbolAddress((void**)&p_h, g_h);
    cudaGetSymbolAddress((void**)&p_qkv, g_qkv);
    cudaGetSymbolAddress((void**)&p_ov, g_ov);
    cudaGetSymbolAddress((void**)&p_lev[0], g_lev0);
    cudaGetSymbolAddress((void**)&p_lev[1], g_lev1);
    cudaGetSymbolAddress((void**)&p_lev[2], g_lev2);
    cudaGetSymbolAddress((void**)&p_lev[3], g_lev3);
    cudaGetSymbolAddress((void**)&p_a2, g_a2);
    cudaGetSymbolAddress((void**)&p_w2stem, g_w2stem);
    cudaGetSymbolAddress((void**)&p_w2qkv, g_w2qkv);
    cudaGetSymbolAddress((void**)&p_w2out, g_w2out);

    const int M = BB * LL;

    // weight splits (small)
    split_stem_wgt_kernel<<<(CC * 512 + 255) / 256, 256>>>(stem_w);
    split_wgt_kernel<<<(3 * CC * CC + 255) / 256, 256>>>(qkv_w, p_w2qkv, 3 * CC * CC, CC);
    split_wgt_kernel<<<(CC * CC + 255) / 256, 256>>>(out_w, p_w2out, CC * CC, CC);

    // stem: h = conv(x) + b  as GEMM  (M x 256) = (M x 1536) * (256 x 1536)^T
    split_stem_act_kernel<<<(M * 512 + 255) / 256, 256>>>(x);
    {
        dim3 grid(CC / 128, M / 128);
        gemm_mma<<<grid, 256>>>(p_a2, p_w2stem, stem_b, p_h, M, CC, 1536);
    }

    // levels
    for (int i = 0; i < NLEV; i++) {
        int l = LL >> i;
        int Mi = BB * l;
        split_act_kernel<<<(Mi * CC + 255) / 256, 256>>>(p_h, p_a2, Mi * CC, CC);
        {
            dim3 grid((3 * CC) / 128, Mi / 128);
            gemm_mma<<<grid, 256>>>(p_a2, p_w2qkv, nullptr, p_qkv, Mi, 3 * CC, 3 * CC);
        }
        attn_kernel<<<Mi / 8, 256>>>(p_h, p_qkv, width_w, width_b, p_ov, l);
        split_act_kernel<<<(Mi * CC + 255) / 256, 256>>>(p_ov, p_a2, Mi * CC, CC);
        {
            dim3 grid(CC / 128, Mi / 128);
            gemm_mma<<<grid, 256>>>(p_a2, p_w2out, nullptr, p_lev[i], Mi, CC, 3 * CC);
        }
        if (i < NLEV - 1) {
            int tot = BB * (l / 2) * CC;
            downsample_kernel<<<(tot + 255) / 256, 256>>>(p_lev[i], p_h, l);
        }
    }

    // global attention + FiLM
    logits_kernel<<<(BB * LL) / 8, 256>>>(query);
    softmax_kernel<<<BB, 256>>>();
    ctx_part_kernel<<<dim3(NLEV, BB, CTX_CHUNKS), CC>>>();
    ctx_reduce_kernel<<<dim3(NLEV, BB), CC>>>();
    film_kernel<<<BB, 2 * CC>>>(film_w, film_b);
    final_kernel<<<(BB * LL * CC + 255) / 256, 256>>>(out);
}

// round 5
// speedup vs baseline: 1.9267x; 1.1912x over previous
#include <cuda_runtime.h>
#include <cuda_bf16.h>
#include <math.h>
#include <stdint.h>

#define BB 2
#define LL 8192
#define CC 256
#define KW 17
#define HALFW 8
#define NLEV 4
#define CTX_CHUNKS 32

__device__ __forceinline__ uint32_t smem_to_u32(const void* p) {
    uint32_t a;
    asm("{ .reg .u64 t; cvta.to.shared.u64 t, %1; cvt.u32.u64 %0, t; }" : "=r"(a) : "l"(p));
    return a;
}

// ================= device scratch =================
__device__ float g_h[BB * LL * CC];
__device__ float g_qkv[BB * LL * 3 * CC];
__device__ float g_ov[BB * LL * CC];
__device__ float g_lev0[BB * LL * CC];
__device__ float g_lev1[BB * (LL / 2) * CC];
__device__ float g_lev2[BB * (LL / 4) * CC];
__device__ float g_lev3[BB * (LL / 8) * CC];
__device__ float g_logits[BB * LL];
__device__ float g_gattn[BB * LL];
__device__ float g_ctxpart[NLEV * BB * CTX_CHUNKS * CC];
__device__ float g_ctx[BB * NLEV * CC];
__device__ float g_film[BB * 2 * CC];

// weights pre-split [hi | lo] along K
__device__ __nv_bfloat16 g_w2stem[CC * 2 * 512];     // 256 x 1024 (K=512)
__device__ __nv_bfloat16 g_w2qkv[3 * CC * 2 * CC];   // 768 x 512  (K=256)
__device__ __nv_bfloat16 g_w2out[CC * 2 * CC];       // 256 x 512  (K=256)

__device__ __forceinline__ float sigmoidf_(float x) { return 1.0f / (1.0f + expf(-x)); }

// ================= weight hi/lo split =================
__global__ void split_wgt2_kernel(const float* __restrict__ X, __nv_bfloat16* __restrict__ Y,
                                  int total, int K) {
    int idx = blockIdx.x * blockDim.x + threadIdx.x;
    if (idx >= total) return;
    int m = idx / K, k = idx - m * K;
    float v = X[idx];
    __nv_bfloat16 h = __float2bfloat16(v);
    __nv_bfloat16 l = __float2bfloat16(v - __bfloat162float(h));
    size_t base = (size_t)m * 2 * K;
    Y[base + k] = h; Y[base + K + k] = l;
}

// stem weight: row o, K=512 logical: k<256 -> stem_w[o,k,0], else stem_w[o,k-256,1]
__global__ void split_stem_wgt2_kernel(const float* __restrict__ stem_w) {
    int idx = blockIdx.x * blockDim.x + threadIdx.x;   // over 256*512
    if (idx >= CC * 512) return;
    int k = idx & 511;
    int o = idx >> 9;
    int i = k & 255, tap = (k < CC) ? 0 : 1;
    float v = stem_w[(size_t)o * 512 + i * 2 + tap];
    __nv_bfloat16 h = __float2bfloat16(v);
    __nv_bfloat16 l = __float2bfloat16(v - __bfloat162float(h));
    size_t base = (size_t)o * 1024;
    g_w2stem[base + k] = h; g_w2stem[base + 512 + k] = l;
}

// ================= fused-split HMMA GEMM =================
// C[M,N] = A[M,K](fp32) * Bw[N,2K](bf16 [hi|lo])^T (+bias), via Ah*Bh + Ah*Bl + Al*Bh.
// 128x128 CTA tile, BK=32, 8 warps (2x4), warp tile 64x32, double-buffered dyn smem.
// stem!=0: A is x[B*L,256]; logical row m = [x[m-1,:] (0 if t==0) | x[m,:]], K=512.
#define BK 32
#define SP 40
#define TILE (128 * SP)
#define GEMM_SMEM (8 * TILE * 2)   // 81920 B

__device__ __forceinline__ void load_a_chunk(const float* __restrict__ A, int stem,
                                             int row, int K, int cbase, float4* av) {
    if (!stem) {
        const float* p = A + (size_t)row * K + cbase;
#pragma unroll
        for (int j = 0; j < 4; j++) av[j] = *reinterpret_cast<const float4*>(p + 4 * j);
    } else {
        int t = row & (LL - 1);
#pragma unroll
        for (int j = 0; j < 4; j++) {
            int col = cbase + 4 * j;
            if (col < CC) {
                av[j] = (t > 0) ? *reinterpret_cast<const float4*>(A + (size_t)(row - 1) * CC + col)
                                : make_float4(0.f, 0.f, 0.f, 0.f);
            } else {
                av[j] = *reinterpret_cast<const float4*>(A + (size_t)row * CC + col - CC);
            }
        }
    }
}

__global__ void __launch_bounds__(256) gemm_fused(const float* __restrict__ A,
                                                  const __nv_bfloat16* __restrict__ Bw,
                                                  const float* __restrict__ bias,
                                                  float* __restrict__ C,
                                                  int M, int N, int K, int stem) {
    extern __shared__ __align__(16) __nv_bfloat16 sm[];
    __nv_bfloat16* pAh = sm;             // [2][TILE]
    __nv_bfloat16* pAl = sm + 2 * TILE;
    __nv_bfloat16* pBh = sm + 4 * TILE;
    __nv_bfloat16* pBl = sm + 6 * TILE;

    const int tid = threadIdx.x;
    const int lane = tid & 31;
    const int wid = tid >> 5;
    const int wm = (wid >> 2) * 64;
    const int wn = (wid & 3) * 32;
    const int m0 = blockIdx.y * 128;
    const int n0 = blockIdx.x * 128;

    float acc[4][4][4];
#pragma unroll
    for (int i = 0; i < 4; i++)
#pragma unroll
        for (int j = 0; j < 4; j++)
#pragma unroll
            for (int r = 0; r < 4; r++) acc[i][j][r] = 0.0f;

    const int lrow = tid >> 1;
    const int lhalf = (tid & 1) * 16;
    const __nv_bfloat16* Bgp = Bw + (size_t)(n0 + lrow) * (2 * K) + lhalf;

    // ---- store helper (expanded inline twice) ----
#define STORE_CHUNK(BUF, AV, BH0, BH1, BL0, BL1) do {                                   \
        uint32_t* _ah = reinterpret_cast<uint32_t*>(pAh + (BUF) * TILE + lrow * SP + lhalf); \
        uint32_t* _al = reinterpret_cast<uint32_t*>(pAl + (BUF) * TILE + lrow * SP + lhalf); \
        _Pragma("unroll")                                                               \
        for (int j = 0; j < 4; j++) {                                                   \
            __nv_bfloat162 h01 = __float22bfloat162_rn(make_float2((AV)[j].x, (AV)[j].y)); \
            __nv_bfloat162 h23 = __float22bfloat162_rn(make_float2((AV)[j].z, (AV)[j].w)); \
            float2 f01 = __bfloat1622float2(h01);                                       \
            float2 f23 = __bfloat1622float2(h23);                                       \
            __nv_bfloat162 l01 = __float22bfloat162_rn(make_float2((AV)[j].x - f01.x, (AV)[j].y - f01.y)); \
            __nv_bfloat162 l23 = __float22bfloat162_rn(make_float2((AV)[j].z - f23.x, (AV)[j].w - f23.y)); \
            _ah[2 * j] = *reinterpret_cast<uint32_t*>(&h01);                            \
            _ah[2 * j + 1] = *reinterpret_cast<uint32_t*>(&h23);                        \
            _al[2 * j] = *reinterpret_cast<uint32_t*>(&l01);                            \
            _al[2 * j + 1] = *reinterpret_cast<uint32_t*>(&l23);                        \
        }                                                                               \
        *reinterpret_cast<uint4*>(pBh + (BUF) * TILE + lrow * SP + lhalf) = BH0;        \
        *reinterpret_cast<uint4*>(pBh + (BUF) * TILE + lrow * SP + lhalf + 8) = BH1;    \
        *reinterpret_cast<uint4*>(pBl + (BUF) * TILE + lrow * SP + lhalf) = BL0;        \
        *reinterpret_cast<uint4*>(pBl + (BUF) * TILE + lrow * SP + lhalf + 8) = BL1;    \
    } while (0)

    // preload chunk 0
    {
        float4 av[4];
        load_a_chunk(A, stem, m0 + lrow, K, 0 + lhalf, av);
        uint4 bh0 = *reinterpret_cast<const uint4*>(Bgp);
        uint4 bh1 = *reinterpret_cast<const uint4*>(Bgp + 8);
        uint4 bl0 = *reinterpret_cast<const uint4*>(Bgp + K);
        uint4 bl1 = *reinterpret_cast<const uint4*>(Bgp + K + 8);
        STORE_CHUNK(0, av, bh0, bh1, bl0, bl1);
    }
    __syncthreads();

    const int NT = K / BK;
    for (int it = 0; it < NT; it++) {
        const int buf = it & 1;
        const bool more = (it + 1) < NT;
        float4 av[4];
        uint4 bh0, bh1, bl0, bl1;
        if (more) {
            const int ko = (it + 1) * BK;
            load_a_chunk(A, stem, m0 + lrow, K, ko + lhalf, av);
            bh0 = *reinterpret_cast<const uint4*>(Bgp + ko);
            bh1 = *reinterpret_cast<const uint4*>(Bgp + ko + 8);
            bl0 = *reinterpret_cast<const uint4*>(Bgp + K + ko);
            bl1 = *reinterpret_cast<const uint4*>(Bgp + K + ko + 8);
        }
#pragma unroll
        for (int ks = 0; ks < 2; ks++) {
            uint32_t ahf[4][4], alf[4][4], bhf[4][2], blf[4][2];
            const int acol = ks * 16 + ((lane >> 4) << 3);
            const int arow = lane & 15;
#pragma unroll
            for (int mt = 0; mt < 4; mt++) {
                uint32_t addr = smem_to_u32(pAh + buf * TILE + (wm + mt * 16 + arow) * SP + acol);
                asm volatile("ldmatrix.sync.aligned.m8n8.x4.shared.b16 {%0,%1,%2,%3}, [%4];"
                             : "=r"(ahf[mt][0]), "=r"(ahf[mt][1]), "=r"(ahf[mt][2]), "=r"(ahf[mt][3])
                             : "r"(addr));
                uint32_t addr2 = smem_to_u32(pAl + buf * TILE + (wm + mt * 16 + arow) * SP + acol);
                asm volatile("ldmatrix.sync.aligned.m8n8.x4.shared.b16 {%0,%1,%2,%3}, [%4];"
                             : "=r"(alf[mt][0]), "=r"(alf[mt][1]), "=r"(alf[mt][2]), "=r"(alf[mt][3])
                             : "r"(addr2));
            }
            const int quad = lane >> 3;
            const int brr = lane & 7;
#pragma unroll
            for (int p = 0; p < 2; p++) {
                int row = wn + (p * 2 + (quad >> 1)) * 8 + brr;
                int col = ks * 16 + (quad & 1) * 8;
                uint32_t addr = smem_to_u32(pBh + buf * TILE + row * SP + col);
                asm volatile("ldmatrix.sync.aligned.m8n8.x4.shared.b16 {%0,%1,%2,%3}, [%4];"
                             : "=r"(bhf[p * 2][0]), "=r"(bhf[p * 2][1]),
                               "=r"(bhf[p * 2 + 1][0]), "=r"(bhf[p * 2 + 1][1])
                             : "r"(addr));
                uint32_t addr2 = smem_to_u32(pBl + buf * TILE + row * SP + col);
                asm volatile("ldmatrix.sync.aligned.m8n8.x4.shared.b16 {%0,%1,%2,%3}, [%4];"
                             : "=r"(blf[p * 2][0]), "=r"(blf[p * 2][1]),
                               "=r"(blf[p * 2 + 1][0]), "=r"(blf[p * 2 + 1][1])
                             : "r"(addr2));
            }
#define DO_MMA(AC, AF, BF)                                                      \
            asm volatile(                                                        \
                "mma.sync.aligned.m16n8k16.row.col.f32.bf16.bf16.f32 "           \
                "{%0,%1,%2,%3}, {%4,%5,%6,%7}, {%8,%9}, {%0,%1,%2,%3};"          \
                : "+f"((AC)[0]), "+f"((AC)[1]), "+f"((AC)[2]), "+f"((AC)[3])     \
                : "r"((AF)[0]), "r"((AF)[1]), "r"((AF)[2]), "r"((AF)[3]),        \
                  "r"((BF)[0]), "r"((BF)[1]))
#pragma unroll
            for (int mt = 0; mt < 4; mt++)
#pragma unroll
                for (int nt = 0; nt < 4; nt++) {
                    DO_MMA(acc[mt][nt], ahf[mt], bhf[nt]);
                    DO_MMA(acc[mt][nt], ahf[mt], blf[nt]);
                    DO_MMA(acc[mt][nt], alf[mt], bhf[nt]);
                }
#undef DO_MMA
        }
        if (more) {
            __syncthreads();
            STORE_CHUNK(buf ^ 1, av, bh0, bh1, bl0, bl1);
            __syncthreads();
        }
    }
#undef STORE_CHUNK

    // epilogue
    const int g = lane >> 2;
    const int t = lane & 3;
#pragma unroll
    for (int mt = 0; mt < 4; mt++) {
#pragma unroll
        for (int nt = 0; nt < 4; nt++) {
            int row = m0 + wm + mt * 16 + g;
            int col = n0 + wn + nt * 8 + 2 * t;
            float b0 = 0.f, b1 = 0.f;
            if (bias) { b0 = bias[col]; b1 = bias[col + 1]; }
            float2 v0, v1;
            v0.x = acc[mt][nt][0] + b0; v0.y = acc[mt][nt][1] + b1;
            v1.x = acc[mt][nt][2] + b0; v1.y = acc[mt][nt][3] + b1;
            *reinterpret_cast<float2*>(C + (size_t)row * N + col) = v0;
            *reinterpret_cast<float2*>(C + (size_t)(row + 8) * N + col) = v1;
        }
    }
}

// ================= windowed attention =================
__global__ void attn_kernel(const float* __restrict__ h,
                            const float* __restrict__ qkv,
                            const float* __restrict__ width_w,
                            const float* __restrict__ width_b,
                            float* __restrict__ ov,
                            int l) {
    int gwarp = (blockIdx.x * blockDim.x + threadIdx.x) >> 5;
    int lane = threadIdx.x & 31;
    if (gwarp >= BB * l) return;
    int b = gwarp / l;
    int t = gwarp - b * l;

    const float* hrow = h + (size_t)gwarp * CC;
    const float* qrow = qkv + (size_t)gwarp * (3 * CC);

    float q[8];
    float wsum = 0.0f;
#pragma unroll
    for (int j = 0; j < 8; j++) {
        int c = lane + 32 * j;
        q[j] = qrow[c];
        wsum = fmaf(hrow[c], width_w[c], wsum);
    }
#pragma unroll
    for (int o = 16; o > 0; o >>= 1) wsum += __shfl_xor_sync(0xffffffffu, wsum, o);
    float width = sigmoidf_(wsum + width_b[0]) * (float)HALFW + 0.5f;

    float scores[KW];
#pragma unroll
    for (int w = 0; w < KW; w++) {
        int kt = t - HALFW + w;
        float s = 0.0f;
        if (kt >= 0 && kt < l) {
            const float* krow = qkv + ((size_t)(b * l + kt)) * (3 * CC) + CC;
#pragma unroll
            for (int j = 0; j < 8; j++) s = fmaf(q[j], krow[lane + 32 * j], s);
        }
#pragma unroll
        for (int o = 16; o > 0; o >>= 1) s += __shfl_xor_sync(0xffffffffu, s, o);
        float rel = fabsf((float)(w - HALFW));
        float mask = sigmoidf_((width - rel) * 5.0f);
        scores[w] = s * 0.0625f - (1.0f - mask) * 10000.0f;
    }

    float mx = scores[0];
#pragma unroll
    for (int w = 1; w < KW; w++) mx = fmaxf(mx, scores[w]);
    float denom = 0.0f;
#pragma unroll
    for (int w = 0; w < KW; w++) { scores[w] = expf(scores[w] - mx); denom += scores[w]; }
    float inv = 1.0f / denom;

    float oacc[8];
    const float* vself = qrow + 2 * CC;
#pragma unroll
    for (int j = 0; j < 8; j++) oacc[j] = vself[lane + 32 * j];
#pragma unroll
    for (int w = 0; w < KW; w++) {
        int kt = t - HALFW + w;
        if (kt < 0 || kt >= l) continue;
        float a = scores[w] * inv;
        const float* vrow = qkv + ((size_t)(b * l + kt)) * (3 * CC) + 2 * CC;
#pragma unroll
        for (int j = 0; j < 8; j++) oacc[j] = fmaf(a, vrow[lane + 32 * j], oacc[j]);
    }
    float* orow = ov + (size_t)gwarp * CC;
#pragma unroll
    for (int j = 0; j < 8; j++) orow[lane + 32 * j] = oacc[j];
}

// ================= mean-pool by 2 =================
__global__ void downsample_kernel(const float* __restrict__ src, float* __restrict__ dst, int lsrc) {
    int idx = blockIdx.x * blockDim.x + threadIdx.x;
    int ldst = lsrc / 2;
    int total = BB * ldst * CC;
    if (idx >= total) return;
    int c = idx % CC;
    int bt = idx / CC;
    int t = bt % ldst;
    int b = bt / ldst;
    const float* s0 = src + ((size_t)(b * lsrc + 2 * t)) * CC + c;
    dst[idx] = 0.5f * (s0[0] + s0[CC]);
}

// ================= global attention logits =================
__global__ void logits_kernel(const float* __restrict__ query) {
    int gwarp = (blockIdx.x * blockDim.x + threadIdx.x) >> 5;
    int lane = threadIdx.x & 31;
    if (gwarp >= BB * LL) return;
    int b = gwarp / LL;
    int t = gwarp - b * LL;
    float s = 0.0f;
#pragma unroll
    for (int j = 0; j < 8; j++) {
        int c = lane + 32 * j;
        s = fmaf(g_lev0[((size_t)(b * LL + t)) * CC + c],            query[c],          s);
        s = fmaf(g_lev1[((size_t)(b * (LL/2) + (t >> 1))) * CC + c], query[CC + c],     s);
        s = fmaf(g_lev2[((size_t)(b * (LL/4) + (t >> 2))) * CC + c], query[2 * CC + c], s);
        s = fmaf(g_lev3[((size_t)(b * (LL/8) + (t >> 3))) * CC + c], query[3 * CC + c], s);
    }
#pragma unroll
    for (int o = 16; o > 0; o >>= 1) s += __shfl_xor_sync(0xffffffffu, s, o);
    if (lane == 0) g_logits[gwarp] = s;
}

// ================= softmax over L per batch =================
__global__ void softmax_kernel() {
    __shared__ float sl[LL];
    __shared__ float red[256];
    int b = blockIdx.x;
    int tid = threadIdx.x;
    const float* lg = g_logits + (size_t)b * LL;
    float mx = -1e30f;
    for (int t = tid; t < LL; t += 256) { float v = lg[t]; sl[t] = v; mx = fmaxf(mx, v); }
    red[tid] = mx; __syncthreads();
    for (int o = 128; o > 0; o >>= 1) { if (tid < o) red[tid] = fmaxf(red[tid], red[tid + o]); __syncthreads(); }
    mx = red[0]; __syncthreads();
    float sum = 0.0f;
    for (int t = tid; t < LL; t += 256) { float e = expf(sl[t] - mx); sl[t] = e; sum += e; }
    red[tid] = sum; __syncthreads();
    for (int o = 128; o > 0; o >>= 1) { if (tid < o) red[tid] += red[tid + o]; __syncthreads(); }
    float inv = 1.0f / red[0];
    for (int t = tid; t < LL; t += 256) g_gattn[(size_t)b * LL + t] = sl[t] * inv;
}

// ================= ctx partial reduction =================
__global__ void ctx_part_kernel() {
    int i = blockIdx.x;
    int b = blockIdx.y;
    int ch = blockIdx.z;
    int c = threadIdx.x;
    const float* lev = (i == 0) ? g_lev0 : (i == 1) ? g_lev1 : (i == 2) ? g_lev2 : g_lev3;
    int li = LL >> i;
    const float* ga = g_gattn + (size_t)b * LL;
    const float* base = lev + (size_t)b * li * CC + c;
    const int span = LL / CTX_CHUNKS;
    const int t0 = ch * span;
    float a0 = 0.f, a1 = 0.f, a2 = 0.f, a3 = 0.f;
    for (int t = t0; t < t0 + span; t += 4) {
        a0 = fmaf(ga[t + 0], base[(size_t)((t + 0) >> i) * CC], a0);
        a1 = fmaf(ga[t + 1], base[(size_t)((t + 1) >> i) * CC], a1);
        a2 = fmaf(ga[t + 2], base[(size_t)((t + 2) >> i) * CC], a2);
        a3 = fmaf(ga[t + 3], base[(size_t)((t + 3) >> i) * CC], a3);
    }
    g_ctxpart[(((size_t)i * BB + b) * CTX_CHUNKS + ch) * CC + c] = (a0 + a1) + (a2 + a3);
}

__global__ void ctx_reduce_kernel() {
    int i = blockIdx.x;
    int b = blockIdx.y;
    int c = threadIdx.x;
    const float* p = g_ctxpart + (((size_t)i * BB + b) * CTX_CHUNKS) * CC + c;
    float s = 0.0f;
#pragma unroll
    for (int ch = 0; ch < CTX_CHUNKS; ch++) s += p[(size_t)ch * CC];
    g_ctx[(size_t)b * (NLEV * CC) + i * CC + c] = s;
}

// ================= FiLM =================
__global__ void film_kernel(const float* __restrict__ film_w, const float* __restrict__ film_b) {
    __shared__ float sc[NLEV * CC];
    int b = blockIdx.x;
    int o = threadIdx.x;
    for (int d = o; d < NLEV * CC; d += 512) sc[d] = g_ctx[(size_t)b * (NLEV * CC) + d];
    __syncthreads();
    const float* wr = film_w + (size_t)o * (NLEV * CC);
    float acc = 0.0f;
#pragma unroll 8
    for (int d = 0; d < NLEV * CC; d++) acc = fmaf(sc[d], wr[d], acc);
    g_film[(size_t)b * (2 * CC) + o] = acc + film_b[o];
}

// ================= final =================
__global__ void final_kernel(float* __restrict__ out) {
    int idx = blockIdx.x * blockDim.x + threadIdx.x;
    if (idx >= BB * LL * CC) return;
    int c = idx % CC;
    int b = idx / (LL * CC);
    float sc = g_film[(size_t)b * (2 * CC) + c];
    float bi = g_film[(size_t)b * (2 * CC) + CC + c];
    out[idx] = fmaf(g_lev0[idx], 1.0f + sc, bi);
}

// ================= launch =================
extern "C" void kernel_launch(void* const* d_in, const int* in_sizes, int n_in,
                              void* d_out, int out_size) {
    const float* x       = (const float*)d_in[0];
    const float* stem_w  = (const float*)d_in[1];
    const float* stem_b  = (const float*)d_in[2];
    const float* qkv_w   = (const float*)d_in[3];
    const float* width_w = (const float*)d_in[4];
    const float* width_b = (const float*)d_in[5];
    const float* out_w   = (const float*)d_in[6];
    const float* query   = (const float*)d_in[7];
    const float* film_w  = (const float*)d_in[8];
    const float* film_b  = (const float*)d_in[9];
    float* out = (float*)d_out;

    cudaFuncSetAttribute(gemm_fused, cudaFuncAttributeMaxDynamicSharedMemorySize, GEMM_SMEM);

    float *p_h, *p_qkv, *p_ov, *p_lev[4];
    __nv_bfloat16 *p_w2stem, *p_w2qkv, *p_w2out;
    cudaGetSymbolAddress((void**)&p_h, g_h);
    cudaGetSymbolAddress((void**)&p_qkv, g_qkv);
    cudaGetSymbolAddress((void**)&p_ov, g_ov);
    cudaGetSymbolAddress((void**)&p_lev[0], g_lev0);
    cudaGetSymbolAddress((void**)&p_lev[1], g_lev1);
    cudaGetSymbolAddress((void**)&p_lev[2], g_lev2);
    cudaGetSymbolAddress((void**)&p_lev[3], g_lev3);
    cudaGetSymbolAddress((void**)&p_w2stem, g_w2stem);
    cudaGetSymbolAddress((void**)&p_w2qkv, g_w2qkv);
    cudaGetSymbolAddress((void**)&p_w2out, g_w2out);

    const int M = BB * LL;

    // weight splits (tiny)
    split_stem_wgt2_kernel<<<(CC * 512 + 255) / 256, 256>>>(stem_w);
    split_wgt2_kernel<<<(3 * CC * CC + 255) / 256, 256>>>(qkv_w, p_w2qkv, 3 * CC * CC, CC);
    split_wgt2_kernel<<<(CC * CC + 255) / 256, 256>>>(out_w, p_w2out, CC * CC, CC);

    // stem: h = conv(x) + b  (fused gather, K=512)
    {
        dim3 grid(CC / 128, M / 128);
        gemm_fused<<<grid, 256, GEMM_SMEM>>>(x, p_w2stem, stem_b, p_h, M, CC, 512, 1);
    }

    // levels
    for (int i = 0; i < NLEV; i++) {
        int l = LL >> i;
        int Mi = BB * l;
        {
            dim3 grid((3 * CC) / 128, Mi / 128);
            gemm_fused<<<grid, 256, GEMM_SMEM>>>(p_h, p_w2qkv, nullptr, p_qkv, Mi, 3 * CC, CC, 0);
        }
        attn_kernel<<<Mi / 8, 256>>>(p_h, p_qkv, width_w, width_b, p_ov, l);
        {
            dim3 grid(CC / 128, Mi / 128);
            gemm_fused<<<grid, 256, GEMM_SMEM>>>(p_ov, p_w2out, nullptr, p_lev[i], Mi, CC, CC, 0);
        }
        if (i < NLEV - 1) {
            int tot = BB * (l / 2) * CC;
            downsample_kernel<<<(tot + 255) / 256, 256>>>(p_lev[i], p_h, l);
        }
    }

    // global attention + FiLM
    logits_kernel<<<(BB * LL) / 8, 256>>>(query);
    softmax_kernel<<<BB, 256>>>();
    ctx_part_kernel<<<dim3(NLEV, BB, CTX_CHUNKS), CC>>>();
    ctx_reduce_kernel<<<dim3(NLEV, BB), CC>>>();
    film_kernel<<<BB, 2 * CC>>>(film_w, film_b);
    final_kernel<<<(BB * LL * CC + 255) / 256, 256>>>(out);
}